// round 12
// baseline (speedup 1.0000x reference)
#include <cuda_runtime.h>
#include <cuda_fp16.h>
#include <cstdint>
#include <math.h>

#define NH   8
#define ND   4096
#define NS   4096
#define DIM  512

// fp16 scratch, heads processed in PAIRS. Total 112 MB (R9-proven footprint).
__device__ __half g_Eh [(size_t)ND * DIM];            // 4 MB
__device__ __half g_Esh[(size_t)NS * DIM];            // 4 MB
__device__ __half g_Fh [(size_t)NS * DIM];            // 4 MB
__device__ __half g_Wqt[(size_t)NH * DIM * DIM];      // 4 MB
__device__ __half g_Wkt[(size_t)NH * DIM * DIM];      // 4 MB
__device__ __half g_Wvt[(size_t)NH * DIM * DIM];      // 4 MB
__device__ __half g_Q  [(size_t)2 * ND * DIM];        // 8 MB
__device__ __half g_K  [(size_t)2 * NS * DIM];        // 8 MB
__device__ __half g_Vt [(size_t)2 * DIM * NS];        // 8 MB  V^T [f][src]
__device__ __half g_S  [(size_t)2 * ND * NS];         // 64 MB

// ---------------------------------------------------------------------------
// Low-level helpers
// ---------------------------------------------------------------------------
__device__ __forceinline__ void cp16(uint32_t s, const void* g) {
    asm volatile("cp.async.cg.shared.global [%0], [%1], 16;" :: "r"(s), "l"(g));
}
__device__ __forceinline__ void cp_commit() {
    asm volatile("cp.async.commit_group;");
}
__device__ __forceinline__ void ldsm_x4(uint32_t& r0, uint32_t& r1,
                                        uint32_t& r2, uint32_t& r3, uint32_t addr) {
    asm volatile("ldmatrix.sync.aligned.m8n8.x4.shared.b16 {%0,%1,%2,%3}, [%4];"
                 : "=r"(r0), "=r"(r1), "=r"(r2), "=r"(r3) : "r"(addr));
}
__device__ __forceinline__ void mma_f16(float* c, const uint32_t* a, const uint32_t* b) {
    asm volatile(
        "mma.sync.aligned.m16n8k16.row.col.f32.f16.f16.f32 "
        "{%0,%1,%2,%3}, {%4,%5,%6,%7}, {%8,%9}, {%0,%1,%2,%3};"
        : "+f"(c[0]), "+f"(c[1]), "+f"(c[2]), "+f"(c[3])
        : "r"(a[0]), "r"(a[1]), "r"(a[2]), "r"(a[3]),
          "r"(b[0]), "r"(b[1]));
}
__device__ __forceinline__ float elu_f(float x) { return x > 0.f ? x : expm1f(x); }

// ===========================================================================
// fp16 NT GEMM: C = A(MxK) @ B(NxK)^T, 128x128 tile, BK=64, 128 threads,
// 4 warps in 2(M) x 2(N), warp tile 64x64 (minimal cross-warp fragment
// redundancy: smem traffic 16KB per k16 step = parity with tensor pipe).
// ===========================================================================
constexpr int BM = 128, BN = 128, BK = 64, GEMM_THREADS = 128, STAGES = 3;
constexpr int STR = 36;                        // row stride in words (32 + 4 pad)
constexpr int TILE_WORDS  = BM * STR;          // 4608
constexpr int STAGE_WORDS = 2 * TILE_WORDS;    // 9216
constexpr int GEMM_SMEM   = STAGES * STAGE_WORDS * 4;  // 110592 B

#define EPI_BIAS_DUAL 0   // C(half) = h(acc + bias[c]); tstore -> C[c][r]
#define EPI_SCALE_H   1   // C(half)[r*N+c] = h(acc * scale)
#define EPI_ELU_ATOM  2   // atomicAdd(C(float)[r*N+c], elu(acc)/NH)

template<int EPI>
__device__ __forceinline__
void gemm_body(const __half* __restrict__ A, const __half* __restrict__ B,
               const float* __restrict__ bias, void* __restrict__ Cv,
               int M, int N, int K, float scale, bool tstore)
{
    extern __shared__ uint32_t smem[];

    const int tid  = threadIdx.x;
    const int lane = tid & 31;
    const int warp = tid >> 5;         // 0..3
    const int wm   = warp >> 1;        // 0..1 -> m offset wm*64
    const int wn   = warp & 1;         // 0..1 -> n offset wn*64
    const int g    = lane >> 2;
    const int t4   = lane & 3;

    const int m0 = blockIdx.y * BM;
    const int n0 = blockIdx.x * BN;

    const uint32_t sbase = (uint32_t)__cvta_generic_to_shared(smem);

    // cp.async mapping: 128 threads, 8 iters each per tile.
    // idx = tid + 128*i -> row = tid>>3 + 16*i, 16B-chunk = tid&7 (invariant)
    const int ld_row = tid >> 3;          // 0..15
    const int ld_c8  = (tid & 7) * 8;     // halves

    const __half* gA = A + (size_t)(m0 + ld_row) * K + ld_c8;
    const __half* gB = B + (size_t)(n0 + ld_row) * K + ld_c8;
    const uint32_t sA0 = sbase + (uint32_t)(ld_row * STR + (tid & 7) * 4) * 4;
    const uint32_t sB0 = sA0 + (uint32_t)TILE_WORDS * 4;

    auto issue = [&](int st, int k0) {
        const uint32_t so = (uint32_t)(st * STAGE_WORDS) * 4;
        #pragma unroll
        for (int i = 0; i < 8; ++i) {
            cp16(sA0 + so + i * 16 * STR * 4, gA + (size_t)i * 16 * K + k0);
            cp16(sB0 + so + i * 16 * STR * 4, gB + (size_t)i * 16 * K + k0);
        }
    };

    // ldmatrix lane bases (words, relative to tile start)
    const int la_row = (lane & 7) + ((lane >> 3) & 1) * 8;
    const int la_wo  = (lane >> 4) * 4;
    const int lb_row = (lane & 7) + (lane >> 4) * 8;
    const int lb_wo  = ((lane >> 3) & 1) * 4;
    const int aBase  = (wm * 64 + la_row) * STR + la_wo;
    const int bBase  = (wn * 64 + lb_row) * STR + lb_wo;

    float acc[4][8][4];
    #pragma unroll
    for (int mi = 0; mi < 4; ++mi)
        #pragma unroll
        for (int ni = 0; ni < 8; ++ni)
            #pragma unroll
            for (int j = 0; j < 4; ++j) acc[mi][ni][j] = 0.f;

    const int nsteps = K / BK;

    #pragma unroll
    for (int s = 0; s < STAGES - 1; ++s) { issue(s, s * BK); cp_commit(); }

    for (int ks = 0; ks < nsteps; ++ks) {
        __syncthreads();   // previous buffer fully consumed
        const int pref = ks + STAGES - 1;
        if (pref < nsteps) issue(pref % STAGES, pref * BK);
        cp_commit();
        asm volatile("cp.async.wait_group %0;" :: "n"(STAGES - 1));
        __syncthreads();   // current buffer visible

        const int st = ks % STAGES;
        const uint32_t stA = sbase + (uint32_t)(st * STAGE_WORDS) * 4;
        const uint32_t stB = stA + (uint32_t)TILE_WORDS * 4;

        #pragma unroll
        for (int kk = 0; kk < BK; kk += 16) {
            const int wb = kk >> 1;
            uint32_t af[4][4], bf[8][2];
            #pragma unroll
            for (int mi = 0; mi < 4; ++mi)
                ldsm_x4(af[mi][0], af[mi][1], af[mi][2], af[mi][3],
                        stA + (uint32_t)(aBase + mi * 16 * STR + wb) * 4);
            #pragma unroll
            for (int np = 0; np < 4; ++np)
                ldsm_x4(bf[2 * np][0], bf[2 * np][1], bf[2 * np + 1][0], bf[2 * np + 1][1],
                        stB + (uint32_t)(bBase + np * 16 * STR + wb) * 4);
            #pragma unroll
            for (int mi = 0; mi < 4; ++mi)
                #pragma unroll
                for (int ni = 0; ni < 8; ++ni)
                    mma_f16(acc[mi][ni], af[mi], bf[ni]);
        }
    }

    // --- epilogue ---
    #pragma unroll
    for (int mi = 0; mi < 4; ++mi) {
        #pragma unroll
        for (int ni = 0; ni < 8; ++ni) {
            const int r = m0 + wm * 64 + mi * 16 + g;
            const int c = n0 + wn * 64 + ni * 8 + 2 * t4;
            const float v0 = acc[mi][ni][0], v1 = acc[mi][ni][1];
            const float v2 = acc[mi][ni][2], v3 = acc[mi][ni][3];
            if (EPI == EPI_BIAS_DUAL) {
                __half* C = (__half*)Cv;
                const float b0 = bias[c], b1 = bias[c + 1];
                if (!tstore) {
                    *reinterpret_cast<__half2*>(C + (size_t)r * N + c) =
                        __floats2half2_rn(v0 + b0, v1 + b1);
                    *reinterpret_cast<__half2*>(C + (size_t)(r + 8) * N + c) =
                        __floats2half2_rn(v2 + b0, v3 + b1);
                } else {          // C[c][r], row stride M
                    C[(size_t)c * M + r]           = __float2half_rn(v0 + b0);
                    C[(size_t)(c + 1) * M + r]     = __float2half_rn(v1 + b1);
                    C[(size_t)c * M + r + 8]       = __float2half_rn(v2 + b0);
                    C[(size_t)(c + 1) * M + r + 8] = __float2half_rn(v3 + b1);
                }
            } else if (EPI == EPI_SCALE_H) {
                __half* C = (__half*)Cv;
                *reinterpret_cast<__half2*>(C + (size_t)r * N + c) =
                    __floats2half2_rn(v0 * scale, v1 * scale);
                *reinterpret_cast<__half2*>(C + (size_t)(r + 8) * N + c) =
                    __floats2half2_rn(v2 * scale, v3 * scale);
            } else {  // EPI_ELU_ATOM
                float* C = (float*)Cv;
                float* p0 = C + (size_t)r * N + c;
                float* p1 = C + (size_t)(r + 8) * N + c;
                atomicAdd(p0,     elu_f(v0) * (1.0f / NH));
                atomicAdd(p0 + 1, elu_f(v1) * (1.0f / NH));
                atomicAdd(p1,     elu_f(v2) * (1.0f / NH));
                atomicAdd(p1 + 1, elu_f(v3) * (1.0f / NH));
            }
        }
    }
}

// All 6 projections of a head pair. z: kind = z%3 (0=Q,1=K,2=V), head = h0+z/3
__global__ __launch_bounds__(GEMM_THREADS, 2)
void proj_all(const __half* __restrict__ Eh, const __half* __restrict__ Esh,
              const __half* __restrict__ Fh,
              const __half* __restrict__ Wqt, const __half* __restrict__ Wkt,
              const __half* __restrict__ Wvt,
              const float* __restrict__ bq, const float* __restrict__ bk,
              const float* __restrict__ bv,
              __half* __restrict__ Q, __half* __restrict__ K,
              __half* __restrict__ Vt, int h0)
{
    const int z    = blockIdx.z;
    const int kind = z % 3;
    const int hp   = z / 3;
    const int head = h0 + hp;
    const size_t sW = (size_t)DIM * DIM;
    const size_t sP = (size_t)ND * DIM;

    const __half* A = (kind == 0) ? Eh : (kind == 1) ? Esh : Fh;
    const __half* W = ((kind == 0) ? Wqt : (kind == 1) ? Wkt : Wvt) + (size_t)head * sW;
    const float* b  = ((kind == 0) ? bq  : (kind == 1) ? bk  : bv ) + (size_t)head * DIM;
    void* C = (kind == 0) ? (void*)(Q + hp * sP)
            : (kind == 1) ? (void*)(K + hp * sP) : (void*)(Vt + hp * sP);

    gemm_body<EPI_BIAS_DUAL>(A, W, b, C, ND, DIM, DIM, 1.f, kind == 2);
}

// Score for a head pair: S[z] = h( (Q[z] @ K[z]^T) * scale )
__global__ __launch_bounds__(GEMM_THREADS, 2)
void score_pair(const __half* __restrict__ Q, const __half* __restrict__ K,
                __half* __restrict__ S, float scale)
{
    const int z = blockIdx.z;
    gemm_body<EPI_SCALE_H>(Q + (size_t)z * ND * DIM, K + (size_t)z * NS * DIM,
                           nullptr, S + (size_t)z * ND * NS, ND, NS, DIM, scale, false);
}

// AV for a head pair: out += elu(S[z] @ Vt[z]^T)/NH  (atomic accumulate)
__global__ __launch_bounds__(GEMM_THREADS, 2)
void av_pair(const __half* __restrict__ S, const __half* __restrict__ Vt,
             float* __restrict__ out)
{
    const int z = blockIdx.z;
    gemm_body<EPI_ELU_ATOM>(S + (size_t)z * ND * NS, Vt + (size_t)z * DIM * NS,
                            nullptr, out, ND, DIM, NS, 1.f, false);
}

// ---------------------------------------------------------------------------
// fp16 row softmax: one block per row of 4096 halves; fp32 math
// ---------------------------------------------------------------------------
__global__ __launch_bounds__(256)
void softmax_h(__half* __restrict__ S)
{
    const int tid = threadIdx.x;
    uint4* row4 = reinterpret_cast<uint4*>(S + (size_t)blockIdx.x * NS);

    uint4 u[2];
    u[0] = row4[tid];
    u[1] = row4[tid + 256];

    float2 f[8];
    const __half2* hp = reinterpret_cast<const __half2*>(u);
    #pragma unroll
    for (int i = 0; i < 8; ++i) f[i] = __half22float2(hp[i]);

    float m = -INFINITY;
    #pragma unroll
    for (int i = 0; i < 8; ++i) m = fmaxf(m, fmaxf(f[i].x, f[i].y));

    __shared__ float red[8];
    #pragma unroll
    for (int o = 16; o > 0; o >>= 1) m = fmaxf(m, __shfl_xor_sync(0xFFFFFFFFu, m, o));
    if ((tid & 31) == 0) red[tid >> 5] = m;
    __syncthreads();
    float M = -INFINITY;
    #pragma unroll
    for (int j = 0; j < 8; ++j) M = fmaxf(M, red[j]);
    __syncthreads();

    float s = 0.f;
    #pragma unroll
    for (int i = 0; i < 8; ++i) {
        f[i].x = __expf(f[i].x - M);
        f[i].y = __expf(f[i].y - M);
        s += f[i].x + f[i].y;
    }
    #pragma unroll
    for (int o = 16; o > 0; o >>= 1) s += __shfl_xor_sync(0xFFFFFFFFu, s, o);
    if ((tid & 31) == 0) red[tid >> 5] = s;
    __syncthreads();
    float tot = 0.f;
    #pragma unroll
    for (int j = 0; j < 8; ++j) tot += red[j];
    const float inv = 1.0f / tot;

    __half2* ho = reinterpret_cast<__half2*>(u);
    #pragma unroll
    for (int i = 0; i < 8; ++i)
        ho[i] = __floats2half2_rn(f[i].x * inv, f[i].y * inv);
    row4[tid]       = u[0];
    row4[tid + 256] = u[1];
}

// ---------------------------------------------------------------------------
// Converters + zero
// ---------------------------------------------------------------------------
__global__ __launch_bounds__(256)
void f2h_kernel(const float* __restrict__ in, __half* __restrict__ out)
{
    const size_t i = ((size_t)blockIdx.x * 256 + threadIdx.x) * 4;
    const float4 v = *reinterpret_cast<const float4*>(in + i);
    __half2 h01 = __floats2half2_rn(v.x, v.y);
    __half2 h23 = __floats2half2_rn(v.z, v.w);
    uint2 packed;
    packed.x = *reinterpret_cast<uint32_t*>(&h01);
    packed.y = *reinterpret_cast<uint32_t*>(&h23);
    *reinterpret_cast<uint2*>(out + i) = packed;
}

__global__ __launch_bounds__(256)
void zero_kernel(float* __restrict__ out)
{
    const size_t i = ((size_t)blockIdx.x * 256 + threadIdx.x) * 4;
    *reinterpret_cast<float4*>(out + i) = make_float4(0.f, 0.f, 0.f, 0.f);
}

__global__ __launch_bounds__(256)
void transpose_f2h(const float* __restrict__ W, __half* __restrict__ Wt)
{
    __shared__ float t[32][33];
    const size_t zo = (size_t)blockIdx.z * DIM * DIM;
    const int tx = threadIdx.x, ty = threadIdx.y;   // block (32, 8)
    const int x  = blockIdx.x * 32 + tx;
    const int y0 = blockIdx.y * 32;
    #pragma unroll
    for (int j = 0; j < 4; ++j)
        t[ty + 8 * j][tx] = W[zo + (size_t)(y0 + ty + 8 * j) * DIM + x];
    __syncthreads();
    const int xo  = blockIdx.y * 32 + tx;
    const int yo0 = blockIdx.x * 32;
    #pragma unroll
    for (int j = 0; j < 4; ++j)
        Wt[zo + (size_t)(yo0 + ty + 8 * j) * DIM + xo] =
            __float2half_rn(t[tx][ty + 8 * j]);
}

// ---------------------------------------------------------------------------
extern "C" void kernel_launch(void* const* d_in, const int* in_sizes, int n_in,
                              void* d_out, int out_size)
{
    const float* emb_dest = (const float*)d_in[0];
    const float* emb_src  = (const float*)d_in[1];
    const float* feat_src = (const float*)d_in[2];
    const float* Wq       = (const float*)d_in[3];
    const float* bq       = (const float*)d_in[4];
    const float* Wk       = (const float*)d_in[5];
    const float* bk       = (const float*)d_in[6];
    const float* Wv       = (const float*)d_in[7];
    const float* bv       = (const float*)d_in[8];
    float* out = (float*)d_out;

    __half *Eh, *Esh, *Fh, *Wqt, *Wkt, *Wvt, *Q, *K, *Vt, *S;
    cudaGetSymbolAddress((void**)&Eh,  g_Eh);
    cudaGetSymbolAddress((void**)&Esh, g_Esh);
    cudaGetSymbolAddress((void**)&Fh,  g_Fh);
    cudaGetSymbolAddress((void**)&Wqt, g_Wqt);
    cudaGetSymbolAddress((void**)&Wkt, g_Wkt);
    cudaGetSymbolAddress((void**)&Wvt, g_Wvt);
    cudaGetSymbolAddress((void**)&Q,   g_Q);
    cudaGetSymbolAddress((void**)&K,   g_K);
    cudaGetSymbolAddress((void**)&Vt,  g_Vt);
    cudaGetSymbolAddress((void**)&S,   g_S);

    cudaFuncSetAttribute(proj_all,   cudaFuncAttributeMaxDynamicSharedMemorySize, GEMM_SMEM);
    cudaFuncSetAttribute(score_pair, cudaFuncAttributeMaxDynamicSharedMemorySize, GEMM_SMEM);
    cudaFuncSetAttribute(av_pair,    cudaFuncAttributeMaxDynamicSharedMemorySize, GEMM_SMEM);

    // One-time fp16 conversion + output zeroing
    f2h_kernel<<<(ND * DIM) / 1024, 256>>>(emb_dest, Eh);
    f2h_kernel<<<(NS * DIM) / 1024, 256>>>(emb_src, Esh);
    f2h_kernel<<<(NS * DIM) / 1024, 256>>>(feat_src, Fh);
    zero_kernel<<<(ND * DIM) / 1024, 256>>>(out);
    const dim3 gT(DIM / 32, DIM / 32, NH), bT(32, 8);
    transpose_f2h<<<gT, bT>>>(Wq, Wqt);
    transpose_f2h<<<gT, bT>>>(Wk, Wkt);
    transpose_f2h<<<gT, bT>>>(Wv, Wvt);

    const dim3 blk(GEMM_THREADS);
    const dim3 gProj(DIM / BN, ND / BM, 6);    // (4, 32, 6)  = 768 blocks
    const dim3 gScore(NS / BN, ND / BM, 2);    // (32, 32, 2) = 2048 blocks
    const dim3 gAV(DIM / BN, ND / BM, 2);      // (4, 32, 2)  = 256 blocks
    const float scale = 0.04419417382415922f;  // 1/sqrt(512)

    for (int h0 = 0; h0 < NH; h0 += 2) {
        proj_all<<<gProj, blk, GEMM_SMEM>>>(
            Eh, Esh, Fh, Wqt, Wkt, Wvt, bq, bk, bv, Q, K, Vt, h0);

        score_pair<<<gScore, blk, GEMM_SMEM>>>(Q, K, S, scale);

        softmax_h<<<2 * ND, 256>>>(S);

        av_pair<<<gAV, blk, GEMM_SMEM>>>(S, Vt, out);
    }
}

// round 15
// speedup vs baseline: 1.0876x; 1.0876x over previous
#include <cuda_runtime.h>
#include <cuda_fp16.h>
#include <cstdint>
#include <math.h>

#define NH   8
#define ND   4096
#define NS   4096
#define DIM  512

// fp16 scratch. Q/K single-buffered (score(i) completes before proj(i+1)
// runs — stream order guarantees it). Only Vt double-buffers, because AV of
// pair i reads Vt while proj of pair i+1 writes the other copy in the SAME
// launch. Total 120 MB (112 proven safe, 136 failed twice).
__device__ __half g_Eh [(size_t)ND * DIM];            // 4 MB
__device__ __half g_Esh[(size_t)NS * DIM];            // 4 MB
__device__ __half g_Fh [(size_t)NS * DIM];            // 4 MB
__device__ __half g_Wqt[(size_t)NH * DIM * DIM];      // 4 MB
__device__ __half g_Wkt[(size_t)NH * DIM * DIM];      // 4 MB
__device__ __half g_Wvt[(size_t)NH * DIM * DIM];      // 4 MB
__device__ __half g_Q  [(size_t)2 * ND * DIM];        // 8 MB  (one pair)
__device__ __half g_K  [(size_t)2 * NS * DIM];        // 8 MB
__device__ __half g_Vt [2][(size_t)2 * DIM * NS];     // 16 MB (double-buffered)
__device__ __half g_S  [(size_t)2 * ND * NS];         // 64 MB

// ---------------------------------------------------------------------------
// Low-level helpers
// ---------------------------------------------------------------------------
__device__ __forceinline__ void cp16(uint32_t s, const void* g) {
    asm volatile("cp.async.cg.shared.global [%0], [%1], 16;" :: "r"(s), "l"(g));
}
__device__ __forceinline__ void cp_commit() {
    asm volatile("cp.async.commit_group;");
}
__device__ __forceinline__ void ldsm_x4(uint32_t& r0, uint32_t& r1,
                                        uint32_t& r2, uint32_t& r3, uint32_t addr) {
    asm volatile("ldmatrix.sync.aligned.m8n8.x4.shared.b16 {%0,%1,%2,%3}, [%4];"
                 : "=r"(r0), "=r"(r1), "=r"(r2), "=r"(r3) : "r"(addr));
}
__device__ __forceinline__ void mma_f16(float* c, const uint32_t* a, const uint32_t* b) {
    asm volatile(
        "mma.sync.aligned.m16n8k16.row.col.f32.f16.f16.f32 "
        "{%0,%1,%2,%3}, {%4,%5,%6,%7}, {%8,%9}, {%0,%1,%2,%3};"
        : "+f"(c[0]), "+f"(c[1]), "+f"(c[2]), "+f"(c[3])
        : "r"(a[0]), "r"(a[1]), "r"(a[2]), "r"(a[3]),
          "r"(b[0]), "r"(b[1]));
}
__device__ __forceinline__ float elu_f(float x) { return x > 0.f ? x : expm1f(x); }

// ===========================================================================
// fp16 NT GEMM (R9-proven config): 128x128 tile, BK=64, 256 threads,
// 8 warps in 2(M) x 4(N), warp tile 64x32, ldmatrix.x4, 3-stage cp.async.
// ===========================================================================
constexpr int BM = 128, BN = 128, BK = 64, GEMM_THREADS = 256, STAGES = 3;
constexpr int STR = 36;
constexpr int TILE_WORDS  = BM * STR;          // 4608
constexpr int STAGE_WORDS = 2 * TILE_WORDS;    // 9216
constexpr int GEMM_SMEM   = STAGES * STAGE_WORDS * 4;  // 110592 B

#define EPI_BIAS_DUAL 0   // C(half) = h(acc + bias[c]); tstore -> C[c][r]
#define EPI_SCALE_H   1   // C(half)[r*N+c] = h(acc * scale)
#define EPI_ELU_ATOM  2   // atomicAdd(C(float)[r*N+c], elu(acc)/NH)

template<int EPI>
__device__ __forceinline__
void gemm_body(const __half* __restrict__ A, const __half* __restrict__ B,
               const float* __restrict__ bias, void* __restrict__ Cv,
               int M, int N, int K, float scale, bool tstore)
{
    extern __shared__ uint32_t smem[];

    const int tid  = threadIdx.x;
    const int lane = tid & 31;
    const int warp = tid >> 5;
    const int wm   = warp >> 2;        // 0..1
    const int wn   = warp & 3;         // 0..3
    const int g    = lane >> 2;
    const int t4   = lane & 3;

    const int m0 = blockIdx.y * BM;
    const int n0 = blockIdx.x * BN;

    const uint32_t sbase = (uint32_t)__cvta_generic_to_shared(smem);

    const int ld_row = tid >> 3;          // 0..31
    const int ld_c8  = (tid & 7) * 8;

    const __half* gA = A + (size_t)(m0 + ld_row) * K + ld_c8;
    const __half* gB = B + (size_t)(n0 + ld_row) * K + ld_c8;
    const uint32_t sA0 = sbase + (uint32_t)(ld_row * STR + (tid & 7) * 4) * 4;
    const uint32_t sB0 = sA0 + (uint32_t)TILE_WORDS * 4;

    auto issue = [&](int st, int k0) {
        const uint32_t so = (uint32_t)(st * STAGE_WORDS) * 4;
        #pragma unroll
        for (int i = 0; i < 4; ++i) {
            cp16(sA0 + so + i * 32 * STR * 4, gA + (size_t)i * 32 * K + k0);
            cp16(sB0 + so + i * 32 * STR * 4, gB + (size_t)i * 32 * K + k0);
        }
    };

    const int la_row = (lane & 7) + ((lane >> 3) & 1) * 8;
    const int la_wo  = (lane >> 4) * 4;
    const int lb_row = (lane & 7) + (lane >> 4) * 8;
    const int lb_wo  = ((lane >> 3) & 1) * 4;
    const int aBase  = (wm * 64 + la_row) * STR + la_wo;
    const int bBase  = (wn * 32 + lb_row) * STR + lb_wo;

    float acc[4][4][4];
    #pragma unroll
    for (int mi = 0; mi < 4; ++mi)
        #pragma unroll
        for (int ni = 0; ni < 4; ++ni)
            #pragma unroll
            for (int j = 0; j < 4; ++j) acc[mi][ni][j] = 0.f;

    const int nsteps = K / BK;

    #pragma unroll
    for (int s = 0; s < STAGES - 1; ++s) { issue(s, s * BK); cp_commit(); }

    for (int ks = 0; ks < nsteps; ++ks) {
        __syncthreads();
        const int pref = ks + STAGES - 1;
        if (pref < nsteps) issue(pref % STAGES, pref * BK);
        cp_commit();
        asm volatile("cp.async.wait_group %0;" :: "n"(STAGES - 1));
        __syncthreads();

        const int st = ks % STAGES;
        const uint32_t stA = sbase + (uint32_t)(st * STAGE_WORDS) * 4;
        const uint32_t stB = stA + (uint32_t)TILE_WORDS * 4;

        #pragma unroll
        for (int kk = 0; kk < BK; kk += 16) {
            const int wb = kk >> 1;
            uint32_t af[4][4], bf[4][2];
            #pragma unroll
            for (int mi = 0; mi < 4; ++mi)
                ldsm_x4(af[mi][0], af[mi][1], af[mi][2], af[mi][3],
                        stA + (uint32_t)(aBase + mi * 16 * STR + wb) * 4);
            #pragma unroll
            for (int np = 0; np < 2; ++np)
                ldsm_x4(bf[2 * np][0], bf[2 * np][1], bf[2 * np + 1][0], bf[2 * np + 1][1],
                        stB + (uint32_t)(bBase + np * 16 * STR + wb) * 4);
            #pragma unroll
            for (int mi = 0; mi < 4; ++mi)
                #pragma unroll
                for (int ni = 0; ni < 4; ++ni)
                    mma_f16(acc[mi][ni], af[mi], bf[ni]);
        }
    }

    // --- epilogue ---
    #pragma unroll
    for (int mi = 0; mi < 4; ++mi) {
        #pragma unroll
        for (int ni = 0; ni < 4; ++ni) {
            const int r = m0 + wm * 64 + mi * 16 + g;
            const int c = n0 + wn * 32 + ni * 8 + 2 * t4;
            const float v0 = acc[mi][ni][0], v1 = acc[mi][ni][1];
            const float v2 = acc[mi][ni][2], v3 = acc[mi][ni][3];
            if (EPI == EPI_BIAS_DUAL) {
                __half* C = (__half*)Cv;
                const float b0 = bias[c], b1 = bias[c + 1];
                if (!tstore) {
                    *reinterpret_cast<__half2*>(C + (size_t)r * N + c) =
                        __floats2half2_rn(v0 + b0, v1 + b1);
                    *reinterpret_cast<__half2*>(C + (size_t)(r + 8) * N + c) =
                        __floats2half2_rn(v2 + b0, v3 + b1);
                } else {          // C[c][r], row stride M
                    C[(size_t)c * M + r]           = __float2half_rn(v0 + b0);
                    C[(size_t)(c + 1) * M + r]     = __float2half_rn(v1 + b1);
                    C[(size_t)c * M + r + 8]       = __float2half_rn(v2 + b0);
                    C[(size_t)(c + 1) * M + r + 8] = __float2half_rn(v3 + b1);
                }
            } else if (EPI == EPI_SCALE_H) {
                __half* C = (__half*)Cv;
                *reinterpret_cast<__half2*>(C + (size_t)r * N + c) =
                    __floats2half2_rn(v0 * scale, v1 * scale);
                *reinterpret_cast<__half2*>(C + (size_t)(r + 8) * N + c) =
                    __floats2half2_rn(v2 * scale, v3 * scale);
            } else {  // EPI_ELU_ATOM
                float* C = (float*)Cv;
                float* p0 = C + (size_t)r * N + c;
                float* p1 = C + (size_t)(r + 8) * N + c;
                atomicAdd(p0,     elu_f(v0) * (1.0f / NH));
                atomicAdd(p0 + 1, elu_f(v1) * (1.0f / NH));
                atomicAdd(p1,     elu_f(v2) * (1.0f / NH));
                atomicAdd(p1 + 1, elu_f(v3) * (1.0f / NH));
            }
        }
    }
}

// Projection dispatch helper: zz in 0..5, kind = zz%3 (Q,K,V), hp = zz/3
__device__ __forceinline__
void proj_slice(int zz, int h0,
                const __half* Eh, const __half* Esh, const __half* Fh,
                const __half* Wqt, const __half* Wkt, const __half* Wvt,
                const float* bq, const float* bk, const float* bv,
                __half* Q, __half* K, __half* Vt)
{
    const int kind = zz % 3;
    const int hp   = zz / 3;
    const int head = h0 + hp;
    const size_t sW = (size_t)DIM * DIM;
    const size_t sP = (size_t)ND * DIM;

    const __half* A = (kind == 0) ? Eh : (kind == 1) ? Esh : Fh;
    const __half* W = ((kind == 0) ? Wqt : (kind == 1) ? Wkt : Wvt) + (size_t)head * sW;
    const float* b  = ((kind == 0) ? bq  : (kind == 1) ? bk  : bv ) + (size_t)head * DIM;
    void* C = (kind == 0) ? (void*)(Q + hp * sP)
            : (kind == 1) ? (void*)(K + hp * sP) : (void*)(Vt + hp * sP);

    gemm_body<EPI_BIAS_DUAL>(A, W, b, C, ND, DIM, DIM, 1.f, kind == 2);
}

// Standalone projections of one head pair (first pair). grid z = 0..5
__global__ __launch_bounds__(GEMM_THREADS, 2)
void proj_all(const __half* __restrict__ Eh, const __half* __restrict__ Esh,
              const __half* __restrict__ Fh,
              const __half* __restrict__ Wqt, const __half* __restrict__ Wkt,
              const __half* __restrict__ Wvt,
              const float* __restrict__ bq, const float* __restrict__ bk,
              const float* __restrict__ bv,
              __half* __restrict__ Q, __half* __restrict__ K,
              __half* __restrict__ Vt, int h0)
{
    proj_slice(blockIdx.z, h0, Eh, Esh, Fh, Wqt, Wkt, Wvt, bq, bk, bv, Q, K, Vt);
}

// Score for a head pair: S[z] = h( (Q[z] @ K[z]^T) * scale ). grid z = 0..1
__global__ __launch_bounds__(GEMM_THREADS, 2)
void score_pair(const __half* __restrict__ Q, const __half* __restrict__ K,
                __half* __restrict__ S, float scale)
{
    const int z = blockIdx.z;
    gemm_body<EPI_SCALE_H>(Q + (size_t)z * ND * DIM, K + (size_t)z * NS * DIM,
                           nullptr, S + (size_t)z * ND * NS, ND, NS, DIM, scale, false);
}

// Fused launch: z<2 -> AV of current pair (atomic accumulate into out);
// z>=2 -> the 6 projections of the NEXT pair (Q/K in place — score already
// done — and Vt into the other parity buffer). grid z = 0..7
__global__ __launch_bounds__(GEMM_THREADS, 2)
void av_proj(const __half* __restrict__ S, const __half* __restrict__ VtCur,
             float* __restrict__ out,
             const __half* __restrict__ Eh, const __half* __restrict__ Esh,
             const __half* __restrict__ Fh,
             const __half* __restrict__ Wqt, const __half* __restrict__ Wkt,
             const __half* __restrict__ Wvt,
             const float* __restrict__ bq, const float* __restrict__ bk,
             const float* __restrict__ bv,
             __half* __restrict__ Q, __half* __restrict__ K,
             __half* __restrict__ VtNext, int h0next)
{
    const int z = blockIdx.z;
    if (z < 2) {
        gemm_body<EPI_ELU_ATOM>(S + (size_t)z * ND * NS, VtCur + (size_t)z * DIM * NS,
                                nullptr, out, ND, DIM, NS, 1.f, false);
    } else {
        proj_slice(z - 2, h0next, Eh, Esh, Fh, Wqt, Wkt, Wvt, bq, bk, bv, Q, K, VtNext);
    }
}

// AV only (last pair). grid z = 0..1
__global__ __launch_bounds__(GEMM_THREADS, 2)
void av_pair(const __half* __restrict__ S, const __half* __restrict__ Vt,
             float* __restrict__ out)
{
    const int z = blockIdx.z;
    gemm_body<EPI_ELU_ATOM>(S + (size_t)z * ND * NS, Vt + (size_t)z * DIM * NS,
                            nullptr, out, ND, DIM, NS, 1.f, false);
}

// ---------------------------------------------------------------------------
// fp16 row softmax: one block per row of 4096 halves; fp32 math
// ---------------------------------------------------------------------------
__global__ __launch_bounds__(256)
void softmax_h(__half* __restrict__ S)
{
    const int tid = threadIdx.x;
    uint4* row4 = reinterpret_cast<uint4*>(S + (size_t)blockIdx.x * NS);

    uint4 u[2];
    u[0] = row4[tid];
    u[1] = row4[tid + 256];

    float2 f[8];
    const __half2* hp = reinterpret_cast<const __half2*>(u);
    #pragma unroll
    for (int i = 0; i < 8; ++i) f[i] = __half22float2(hp[i]);

    float m = -INFINITY;
    #pragma unroll
    for (int i = 0; i < 8; ++i) m = fmaxf(m, fmaxf(f[i].x, f[i].y));

    __shared__ float red[8];
    #pragma unroll
    for (int o = 16; o > 0; o >>= 1) m = fmaxf(m, __shfl_xor_sync(0xFFFFFFFFu, m, o));
    if ((tid & 31) == 0) red[tid >> 5] = m;
    __syncthreads();
    float M = -INFINITY;
    #pragma unroll
    for (int j = 0; j < 8; ++j) M = fmaxf(M, red[j]);
    __syncthreads();

    float s = 0.f;
    #pragma unroll
    for (int i = 0; i < 8; ++i) {
        f[i].x = __expf(f[i].x - M);
        f[i].y = __expf(f[i].y - M);
        s += f[i].x + f[i].y;
    }
    #pragma unroll
    for (int o = 16; o > 0; o >>= 1) s += __shfl_xor_sync(0xFFFFFFFFu, s, o);
    if ((tid & 31) == 0) red[tid >> 5] = s;
    __syncthreads();
    float tot = 0.f;
    #pragma unroll
    for (int j = 0; j < 8; ++j) tot += red[j];
    const float inv = 1.0f / tot;

    __half2* ho = reinterpret_cast<__half2*>(u);
    #pragma unroll
    for (int i = 0; i < 8; ++i)
        ho[i] = __floats2half2_rn(f[i].x * inv, f[i].y * inv);
    row4[tid]       = u[0];
    row4[tid + 256] = u[1];
}

// ---------------------------------------------------------------------------
// Converters + zero
// ---------------------------------------------------------------------------
__global__ __launch_bounds__(256)
void f2h_kernel(const float* __restrict__ in, __half* __restrict__ out)
{
    const size_t i = ((size_t)blockIdx.x * 256 + threadIdx.x) * 4;
    const float4 v = *reinterpret_cast<const float4*>(in + i);
    __half2 h01 = __floats2half2_rn(v.x, v.y);
    __half2 h23 = __floats2half2_rn(v.z, v.w);
    uint2 packed;
    packed.x = *reinterpret_cast<uint32_t*>(&h01);
    packed.y = *reinterpret_cast<uint32_t*>(&h23);
    *reinterpret_cast<uint2*>(out + i) = packed;
}

__global__ __launch_bounds__(256)
void zero_kernel(float* __restrict__ out)
{
    const size_t i = ((size_t)blockIdx.x * 256 + threadIdx.x) * 4;
    *reinterpret_cast<float4*>(out + i) = make_float4(0.f, 0.f, 0.f, 0.f);
}

__global__ __launch_bounds__(256)
void transpose_f2h(const float* __restrict__ W, __half* __restrict__ Wt)
{
    __shared__ float t[32][33];
    const size_t zo = (size_t)blockIdx.z * DIM * DIM;
    const int tx = threadIdx.x, ty = threadIdx.y;   // block (32, 8)
    const int x  = blockIdx.x * 32 + tx;
    const int y0 = blockIdx.y * 32;
    #pragma unroll
    for (int j = 0; j < 4; ++j)
        t[ty + 8 * j][tx] = W[zo + (size_t)(y0 + ty + 8 * j) * DIM + x];
    __syncthreads();
    const int xo  = blockIdx.y * 32 + tx;
    const int yo0 = blockIdx.x * 32;
    #pragma unroll
    for (int j = 0; j < 4; ++j)
        Wt[zo + (size_t)(yo0 + ty + 8 * j) * DIM + xo] =
            __float2half_rn(t[tx][ty + 8 * j]);
}

// ---------------------------------------------------------------------------
extern "C" void kernel_launch(void* const* d_in, const int* in_sizes, int n_in,
                              void* d_out, int out_size)
{
    const float* emb_dest = (const float*)d_in[0];
    const float* emb_src  = (const float*)d_in[1];
    const float* feat_src = (const float*)d_in[2];
    const float* Wq       = (const float*)d_in[3];
    const float* bq       = (const float*)d_in[4];
    const float* Wk       = (const float*)d_in[5];
    const float* bk       = (const float*)d_in[6];
    const float* Wv       = (const float*)d_in[7];
    const float* bv       = (const float*)d_in[8];
    float* out = (float*)d_out;

    __half *Eh, *Esh, *Fh, *Wqt, *Wkt, *Wvt, *Q, *K, *Vtb, *S;
    cudaGetSymbolAddress((void**)&Eh,  g_Eh);
    cudaGetSymbolAddress((void**)&Esh, g_Esh);
    cudaGetSymbolAddress((void**)&Fh,  g_Fh);
    cudaGetSymbolAddress((void**)&Wqt, g_Wqt);
    cudaGetSymbolAddress((void**)&Wkt, g_Wkt);
    cudaGetSymbolAddress((void**)&Wvt, g_Wvt);
    cudaGetSymbolAddress((void**)&Q,   g_Q);
    cudaGetSymbolAddress((void**)&K,   g_K);
    cudaGetSymbolAddress((void**)&Vtb, g_Vt);
    cudaGetSymbolAddress((void**)&S,   g_S);

    const size_t VB = (size_t)2 * DIM * NS;   // per-parity Vt buffer elements
    __half* Vtp[2] = {Vtb, Vtb + VB};

    cudaFuncSetAttribute(proj_all,   cudaFuncAttributeMaxDynamicSharedMemorySize, GEMM_SMEM);
    cudaFuncSetAttribute(score_pair, cudaFuncAttributeMaxDynamicSharedMemorySize, GEMM_SMEM);
    cudaFuncSetAttribute(av_proj,    cudaFuncAttributeMaxDynamicSharedMemorySize, GEMM_SMEM);
    cudaFuncSetAttribute(av_pair,    cudaFuncAttributeMaxDynamicSharedMemorySize, GEMM_SMEM);

    // One-time fp16 conversion + output zeroing
    f2h_kernel<<<(ND * DIM) / 1024, 256>>>(emb_dest, Eh);
    f2h_kernel<<<(NS * DIM) / 1024, 256>>>(emb_src, Esh);
    f2h_kernel<<<(NS * DIM) / 1024, 256>>>(feat_src, Fh);
    zero_kernel<<<(ND * DIM) / 1024, 256>>>(out);
    const dim3 gT(DIM / 32, DIM / 32, NH), bT(32, 8);
    transpose_f2h<<<gT, bT>>>(Wq, Wqt);
    transpose_f2h<<<gT, bT>>>(Wk, Wkt);
    transpose_f2h<<<gT, bT>>>(Wv, Wvt);

    const dim3 blk(GEMM_THREADS);
    const dim3 gProj(DIM / BN, ND / BM, 6);     // (4, 32, 6)
    const dim3 gScore(NS / BN, ND / BM, 2);     // (32, 32, 2)
    const dim3 gAVProj(DIM / BN, ND / BM, 8);   // (4, 32, 8) = 1024 blocks
    const dim3 gAV(DIM / BN, ND / BM, 2);       // (4, 32, 2)
    const float scale = 0.04419417382415922f;   // 1/sqrt(512)

    // Prologue: projections for pair 0 (Vt into parity buffer 0)
    proj_all<<<gProj, blk, GEMM_SMEM>>>(
        Eh, Esh, Fh, Wqt, Wkt, Wvt, bq, bk, bv, Q, K, Vtp[0], 0);

    for (int i = 0; i < 4; ++i) {
        const int p = i & 1, pn = p ^ 1;

        score_pair<<<gScore, blk, GEMM_SMEM>>>(Q, K, S, scale);
        softmax_h<<<2 * ND, 256>>>(S);

        if (i < 3) {
            // AV of pair i fused with projections of pair i+1.
            // Q/K overwritten in place (score done); Vt goes to other buffer.
            av_proj<<<gAVProj, blk, GEMM_SMEM>>>(
                S, Vtp[p], out,
                Eh, Esh, Fh, Wqt, Wkt, Wvt, bq, bk, bv,
                Q, K, Vtp[pn], 2 * (i + 1));
        } else {
            av_pair<<<gAV, blk, GEMM_SMEM>>>(S, Vtp[p], out);
        }
    }
}

// round 16
// speedup vs baseline: 1.0972x; 1.0088x over previous
#include <cuda_runtime.h>
#include <cuda_fp16.h>
#include <cstdint>
#include <math.h>

#define NH   8
#define ND   4096
#define NS   4096
#define DIM  512

// fp16 scratch. Q/K single-buffered (score(i) completes before proj(i+1));
// Vt double-buffered (AV reads old while fused proj writes new). 120 MB.
__device__ __half g_Eh [(size_t)ND * DIM];            // 4 MB
__device__ __half g_Esh[(size_t)NS * DIM];            // 4 MB
__device__ __half g_Fh [(size_t)NS * DIM];            // 4 MB
__device__ __half g_Wqt[(size_t)NH * DIM * DIM];      // 4 MB
__device__ __half g_Wkt[(size_t)NH * DIM * DIM];      // 4 MB
__device__ __half g_Wvt[(size_t)NH * DIM * DIM];      // 4 MB
__device__ __half g_Q  [(size_t)2 * ND * DIM];        // 8 MB  (one pair)
__device__ __half g_K  [(size_t)2 * NS * DIM];        // 8 MB
__device__ __half g_Vt [2][(size_t)2 * DIM * NS];     // 16 MB (double-buffered)
__device__ __half g_S  [(size_t)2 * ND * NS];         // 64 MB

// ---------------------------------------------------------------------------
// Low-level helpers
// ---------------------------------------------------------------------------
__device__ __forceinline__ void cp16(uint32_t s, const void* g) {
    asm volatile("cp.async.cg.shared.global [%0], [%1], 16;" :: "r"(s), "l"(g));
}
__device__ __forceinline__ void cp_commit() {
    asm volatile("cp.async.commit_group;");
}
__device__ __forceinline__ void ldsm_x4(uint32_t& r0, uint32_t& r1,
                                        uint32_t& r2, uint32_t& r3, uint32_t addr) {
    asm volatile("ldmatrix.sync.aligned.m8n8.x4.shared.b16 {%0,%1,%2,%3}, [%4];"
                 : "=r"(r0), "=r"(r1), "=r"(r2), "=r"(r3) : "r"(addr));
}
__device__ __forceinline__ void mma_f16(float* c, const uint32_t* a, const uint32_t* b) {
    asm volatile(
        "mma.sync.aligned.m16n8k16.row.col.f32.f16.f16.f32 "
        "{%0,%1,%2,%3}, {%4,%5,%6,%7}, {%8,%9}, {%0,%1,%2,%3};"
        : "+f"(c[0]), "+f"(c[1]), "+f"(c[2]), "+f"(c[3])
        : "r"(a[0]), "r"(a[1]), "r"(a[2]), "r"(a[3]),
          "r"(b[0]), "r"(b[1]));
}
__device__ __forceinline__ float elu_f(float x) { return x > 0.f ? x : expm1f(x); }

// ===========================================================================
// fp16 NT GEMM: 128x128 tile, BK=64, 256 threads, 8 warps (2M x 4N),
// warp tile 64x32, ldmatrix.x4, 3-stage cp.async, SINGLE sync per k-step.
//
// Single-barrier correctness: prefetch at iter ks targets slot (ks-1)%3 —
// the buffer consumed at iter ks-1. compute(ks-1) precedes the barrier of
// iter ks in every warp's program order, so after the barrier that buffer
// is dead. wait_group(1) at iter ks leaves only load ks+1 pending => load
// ks is resident before its ldmatrix reads.
// ===========================================================================
constexpr int BM = 128, BN = 128, BK = 64, GEMM_THREADS = 256, STAGES = 3;
constexpr int STR = 36;
constexpr int TILE_WORDS  = BM * STR;          // 4608
constexpr int STAGE_WORDS = 2 * TILE_WORDS;    // 9216
constexpr int GEMM_SMEM   = STAGES * STAGE_WORDS * 4;  // 110592 B

#define EPI_BIAS_DUAL 0   // C(half) = h(acc + bias[c]); tstore -> C[c][r]
#define EPI_SCALE_H   1   // C(half)[r*N+c] = h(acc * scale)
#define EPI_ELU_ATOM  2   // atomicAdd(C(float)[r*N+c], elu(acc)/NH)

template<int EPI>
__device__ __forceinline__
void gemm_body(const __half* __restrict__ A, const __half* __restrict__ B,
               const float* __restrict__ bias, void* __restrict__ Cv,
               int M, int N, int K, float scale, bool tstore)
{
    extern __shared__ uint32_t smem[];

    const int tid  = threadIdx.x;
    const int lane = tid & 31;
    const int warp = tid >> 5;
    const int wm   = warp >> 2;        // 0..1
    const int wn   = warp & 3;         // 0..3
    const int g    = lane >> 2;
    const int t4   = lane & 3;

    const int m0 = blockIdx.y * BM;
    const int n0 = blockIdx.x * BN;

    const uint32_t sbase = (uint32_t)__cvta_generic_to_shared(smem);

    const int ld_row = tid >> 3;          // 0..31
    const int ld_c8  = (tid & 7) * 8;

    const __half* gA = A + (size_t)(m0 + ld_row) * K + ld_c8;
    const __half* gB = B + (size_t)(n0 + ld_row) * K + ld_c8;
    const uint32_t sA0 = sbase + (uint32_t)(ld_row * STR + (tid & 7) * 4) * 4;
    const uint32_t sB0 = sA0 + (uint32_t)TILE_WORDS * 4;

    auto issue = [&](int st, int k0) {
        const uint32_t so = (uint32_t)(st * STAGE_WORDS) * 4;
        #pragma unroll
        for (int i = 0; i < 4; ++i) {
            cp16(sA0 + so + i * 32 * STR * 4, gA + (size_t)i * 32 * K + k0);
            cp16(sB0 + so + i * 32 * STR * 4, gB + (size_t)i * 32 * K + k0);
        }
    };

    const int la_row = (lane & 7) + ((lane >> 3) & 1) * 8;
    const int la_wo  = (lane >> 4) * 4;
    const int lb_row = (lane & 7) + (lane >> 4) * 8;
    const int lb_wo  = ((lane >> 3) & 1) * 4;
    const int aBase  = (wm * 64 + la_row) * STR + la_wo;
    const int bBase  = (wn * 32 + lb_row) * STR + lb_wo;

    float acc[4][4][4];
    #pragma unroll
    for (int mi = 0; mi < 4; ++mi)
        #pragma unroll
        for (int ni = 0; ni < 4; ++ni)
            #pragma unroll
            for (int j = 0; j < 4; ++j) acc[mi][ni][j] = 0.f;

    const int nsteps = K / BK;

    #pragma unroll
    for (int s = 0; s < STAGES - 1; ++s) { issue(s, s * BK); cp_commit(); }

    for (int ks = 0; ks < nsteps; ++ks) {
        asm volatile("cp.async.wait_group %0;" :: "n"(STAGES - 2));
        __syncthreads();   // load ks resident for all; buffer ks-1 dead

        const int pref = ks + STAGES - 1;
        if (pref < nsteps) issue(pref % STAGES, pref * BK);
        cp_commit();       // exactly one group per iteration (may be empty)

        const int st = ks % STAGES;
        const uint32_t stA = sbase + (uint32_t)(st * STAGE_WORDS) * 4;
        const uint32_t stB = stA + (uint32_t)TILE_WORDS * 4;

        #pragma unroll
        for (int kk = 0; kk < BK; kk += 16) {
            const int wb = kk >> 1;
            uint32_t af[4][4], bf[4][2];
            #pragma unroll
            for (int mi = 0; mi < 4; ++mi)
                ldsm_x4(af[mi][0], af[mi][1], af[mi][2], af[mi][3],
                        stA + (uint32_t)(aBase + mi * 16 * STR + wb) * 4);
            #pragma unroll
            for (int np = 0; np < 2; ++np)
                ldsm_x4(bf[2 * np][0], bf[2 * np][1], bf[2 * np + 1][0], bf[2 * np + 1][1],
                        stB + (uint32_t)(bBase + np * 16 * STR + wb) * 4);
            #pragma unroll
            for (int mi = 0; mi < 4; ++mi)
                #pragma unroll
                for (int ni = 0; ni < 4; ++ni)
                    mma_f16(acc[mi][ni], af[mi], bf[ni]);
        }
    }

    // --- epilogue ---
    #pragma unroll
    for (int mi = 0; mi < 4; ++mi) {
        #pragma unroll
        for (int ni = 0; ni < 4; ++ni) {
            const int r = m0 + wm * 64 + mi * 16 + g;
            const int c = n0 + wn * 32 + ni * 8 + 2 * t4;
            const float v0 = acc[mi][ni][0], v1 = acc[mi][ni][1];
            const float v2 = acc[mi][ni][2], v3 = acc[mi][ni][3];
            if (EPI == EPI_BIAS_DUAL) {
                __half* C = (__half*)Cv;
                const float b0 = bias[c], b1 = bias[c + 1];
                if (!tstore) {
                    *reinterpret_cast<__half2*>(C + (size_t)r * N + c) =
                        __floats2half2_rn(v0 + b0, v1 + b1);
                    *reinterpret_cast<__half2*>(C + (size_t)(r + 8) * N + c) =
                        __floats2half2_rn(v2 + b0, v3 + b1);
                } else {          // C[c][r], row stride M
                    C[(size_t)c * M + r]           = __float2half_rn(v0 + b0);
                    C[(size_t)(c + 1) * M + r]     = __float2half_rn(v1 + b1);
                    C[(size_t)c * M + r + 8]       = __float2half_rn(v2 + b0);
                    C[(size_t)(c + 1) * M + r + 8] = __float2half_rn(v3 + b1);
                }
            } else if (EPI == EPI_SCALE_H) {
                __half* C = (__half*)Cv;
                *reinterpret_cast<__half2*>(C + (size_t)r * N + c) =
                    __floats2half2_rn(v0 * scale, v1 * scale);
                *reinterpret_cast<__half2*>(C + (size_t)(r + 8) * N + c) =
                    __floats2half2_rn(v2 * scale, v3 * scale);
            } else {  // EPI_ELU_ATOM
                float* C = (float*)Cv;
                float* p0 = C + (size_t)r * N + c;
                float* p1 = C + (size_t)(r + 8) * N + c;
                atomicAdd(p0,     elu_f(v0) * (1.0f / NH));
                atomicAdd(p0 + 1, elu_f(v1) * (1.0f / NH));
                atomicAdd(p1,     elu_f(v2) * (1.0f / NH));
                atomicAdd(p1 + 1, elu_f(v3) * (1.0f / NH));
            }
        }
    }
}

// Projection dispatch helper: zz in 0..5, kind = zz%3 (Q,K,V), hp = zz/3
__device__ __forceinline__
void proj_slice(int zz, int h0,
                const __half* Eh, const __half* Esh, const __half* Fh,
                const __half* Wqt, const __half* Wkt, const __half* Wvt,
                const float* bq, const float* bk, const float* bv,
                __half* Q, __half* K, __half* Vt)
{
    const int kind = zz % 3;
    const int hp   = zz / 3;
    const int head = h0 + hp;
    const size_t sW = (size_t)DIM * DIM;
    const size_t sP = (size_t)ND * DIM;

    const __half* A = (kind == 0) ? Eh : (kind == 1) ? Esh : Fh;
    const __half* W = ((kind == 0) ? Wqt : (kind == 1) ? Wkt : Wvt) + (size_t)head * sW;
    const float* b  = ((kind == 0) ? bq  : (kind == 1) ? bk  : bv ) + (size_t)head * DIM;
    void* C = (kind == 0) ? (void*)(Q + hp * sP)
            : (kind == 1) ? (void*)(K + hp * sP) : (void*)(Vt + hp * sP);

    gemm_body<EPI_BIAS_DUAL>(A, W, b, C, ND, DIM, DIM, 1.f, kind == 2);
}

// Standalone projections of one head pair (first pair). grid z = 0..5
__global__ __launch_bounds__(GEMM_THREADS, 2)
void proj_all(const __half* __restrict__ Eh, const __half* __restrict__ Esh,
              const __half* __restrict__ Fh,
              const __half* __restrict__ Wqt, const __half* __restrict__ Wkt,
              const __half* __restrict__ Wvt,
              const float* __restrict__ bq, const float* __restrict__ bk,
              const float* __restrict__ bv,
              __half* __restrict__ Q, __half* __restrict__ K,
              __half* __restrict__ Vt, int h0)
{
    proj_slice(blockIdx.z, h0, Eh, Esh, Fh, Wqt, Wkt, Wvt, bq, bk, bv, Q, K, Vt);
}

// Score for a head pair: S[z] = h( (Q[z] @ K[z]^T) * scale ). grid z = 0..1
__global__ __launch_bounds__(GEMM_THREADS, 2)
void score_pair(const __half* __restrict__ Q, const __half* __restrict__ K,
                __half* __restrict__ S, float scale)
{
    const int z = blockIdx.z;
    gemm_body<EPI_SCALE_H>(Q + (size_t)z * ND * DIM, K + (size_t)z * NS * DIM,
                           nullptr, S + (size_t)z * ND * NS, ND, NS, DIM, scale, false);
}

// Fused launch: z<2 -> AV of current pair (atomic accumulate into out);
// z>=2 -> the 6 projections of the NEXT pair (Q/K in place — score already
// done — and Vt into the other parity buffer). grid z = 0..7
__global__ __launch_bounds__(GEMM_THREADS, 2)
void av_proj(const __half* __restrict__ S, const __half* __restrict__ VtCur,
             float* __restrict__ out,
             const __half* __restrict__ Eh, const __half* __restrict__ Esh,
             const __half* __restrict__ Fh,
             const __half* __restrict__ Wqt, const __half* __restrict__ Wkt,
             const __half* __restrict__ Wvt,
             const float* __restrict__ bq, const float* __restrict__ bk,
             const float* __restrict__ bv,
             __half* __restrict__ Q, __half* __restrict__ K,
             __half* __restrict__ VtNext, int h0next)
{
    const int z = blockIdx.z;
    if (z < 2) {
        gemm_body<EPI_ELU_ATOM>(S + (size_t)z * ND * NS, VtCur + (size_t)z * DIM * NS,
                                nullptr, out, ND, DIM, NS, 1.f, false);
    } else {
        proj_slice(z - 2, h0next, Eh, Esh, Fh, Wqt, Wkt, Wvt, bq, bk, bv, Q, K, VtNext);
    }
}

// AV only (last pair). grid z = 0..1
__global__ __launch_bounds__(GEMM_THREADS, 2)
void av_pair(const __half* __restrict__ S, const __half* __restrict__ Vt,
             float* __restrict__ out)
{
    const int z = blockIdx.z;
    gemm_body<EPI_ELU_ATOM>(S + (size_t)z * ND * NS, Vt + (size_t)z * DIM * NS,
                            nullptr, out, ND, DIM, NS, 1.f, false);
}

// ---------------------------------------------------------------------------
// fp16 row softmax: one block per row of 4096 halves; fp32 math
// ---------------------------------------------------------------------------
__global__ __launch_bounds__(256)
void softmax_h(__half* __restrict__ S)
{
    const int tid = threadIdx.x;
    uint4* row4 = reinterpret_cast<uint4*>(S + (size_t)blockIdx.x * NS);

    uint4 u[2];
    u[0] = row4[tid];
    u[1] = row4[tid + 256];

    float2 f[8];
    const __half2* hp = reinterpret_cast<const __half2*>(u);
    #pragma unroll
    for (int i = 0; i < 8; ++i) f[i] = __half22float2(hp[i]);

    float m = -INFINITY;
    #pragma unroll
    for (int i = 0; i < 8; ++i) m = fmaxf(m, fmaxf(f[i].x, f[i].y));

    __shared__ float red[8];
    #pragma unroll
    for (int o = 16; o > 0; o >>= 1) m = fmaxf(m, __shfl_xor_sync(0xFFFFFFFFu, m, o));
    if ((tid & 31) == 0) red[tid >> 5] = m;
    __syncthreads();
    float M = -INFINITY;
    #pragma unroll
    for (int j = 0; j < 8; ++j) M = fmaxf(M, red[j]);
    __syncthreads();

    float s = 0.f;
    #pragma unroll
    for (int i = 0; i < 8; ++i) {
        f[i].x = __expf(f[i].x - M);
        f[i].y = __expf(f[i].y - M);
        s += f[i].x + f[i].y;
    }
    #pragma unroll
    for (int o = 16; o > 0; o >>= 1) s += __shfl_xor_sync(0xFFFFFFFFu, s, o);
    if ((tid & 31) == 0) red[tid >> 5] = s;
    __syncthreads();
    float tot = 0.f;
    #pragma unroll
    for (int j = 0; j < 8; ++j) tot += red[j];
    const float inv = 1.0f / tot;

    __half2* ho = reinterpret_cast<__half2*>(u);
    #pragma unroll
    for (int i = 0; i < 8; ++i)
        ho[i] = __floats2half2_rn(f[i].x * inv, f[i].y * inv);
    row4[tid]       = u[0];
    row4[tid + 256] = u[1];
}

// ---------------------------------------------------------------------------
// Converters + zero
// ---------------------------------------------------------------------------
__global__ __launch_bounds__(256)
void f2h_kernel(const float* __restrict__ in, __half* __restrict__ out)
{
    const size_t i = ((size_t)blockIdx.x * 256 + threadIdx.x) * 4;
    const float4 v = *reinterpret_cast<const float4*>(in + i);
    __half2 h01 = __floats2half2_rn(v.x, v.y);
    __half2 h23 = __floats2half2_rn(v.z, v.w);
    uint2 packed;
    packed.x = *reinterpret_cast<uint32_t*>(&h01);
    packed.y = *reinterpret_cast<uint32_t*>(&h23);
    *reinterpret_cast<uint2*>(out + i) = packed;
}

__global__ __launch_bounds__(256)
void zero_kernel(float* __restrict__ out)
{
    const size_t i = ((size_t)blockIdx.x * 256 + threadIdx.x) * 4;
    *reinterpret_cast<float4*>(out + i) = make_float4(0.f, 0.f, 0.f, 0.f);
}

__global__ __launch_bounds__(256)
void transpose_f2h(const float* __restrict__ W, __half* __restrict__ Wt)
{
    __shared__ float t[32][33];
    const size_t zo = (size_t)blockIdx.z * DIM * DIM;
    const int tx = threadIdx.x, ty = threadIdx.y;   // block (32, 8)
    const int x  = blockIdx.x * 32 + tx;
    const int y0 = blockIdx.y * 32;
    #pragma unroll
    for (int j = 0; j < 4; ++j)
        t[ty + 8 * j][tx] = W[zo + (size_t)(y0 + ty + 8 * j) * DIM + x];
    __syncthreads();
    const int xo  = blockIdx.y * 32 + tx;
    const int yo0 = blockIdx.x * 32;
    #pragma unroll
    for (int j = 0; j < 4; ++j)
        Wt[zo + (size_t)(yo0 + ty + 8 * j) * DIM + xo] =
            __float2half_rn(t[tx][ty + 8 * j]);
}

// ---------------------------------------------------------------------------
extern "C" void kernel_launch(void* const* d_in, const int* in_sizes, int n_in,
                              void* d_out, int out_size)
{
    const float* emb_dest = (const float*)d_in[0];
    const float* emb_src  = (const float*)d_in[1];
    const float* feat_src = (const float*)d_in[2];
    const float* Wq       = (const float*)d_in[3];
    const float* bq       = (const float*)d_in[4];
    const float* Wk       = (const float*)d_in[5];
    const float* bk       = (const float*)d_in[6];
    const float* Wv       = (const float*)d_in[7];
    const float* bv       = (const float*)d_in[8];
    float* out = (float*)d_out;

    __half *Eh, *Esh, *Fh, *Wqt, *Wkt, *Wvt, *Q, *K, *Vtb, *S;
    cudaGetSymbolAddress((void**)&Eh,  g_Eh);
    cudaGetSymbolAddress((void**)&Esh, g_Esh);
    cudaGetSymbolAddress((void**)&Fh,  g_Fh);
    cudaGetSymbolAddress((void**)&Wqt, g_Wqt);
    cudaGetSymbolAddress((void**)&Wkt, g_Wkt);
    cudaGetSymbolAddress((void**)&Wvt, g_Wvt);
    cudaGetSymbolAddress((void**)&Q,   g_Q);
    cudaGetSymbolAddress((void**)&K,   g_K);
    cudaGetSymbolAddress((void**)&Vtb, g_Vt);
    cudaGetSymbolAddress((void**)&S,   g_S);

    const size_t VB = (size_t)2 * DIM * NS;   // per-parity Vt buffer elements
    __half* Vtp[2] = {Vtb, Vtb + VB};

    cudaFuncSetAttribute(proj_all,   cudaFuncAttributeMaxDynamicSharedMemorySize, GEMM_SMEM);
    cudaFuncSetAttribute(score_pair, cudaFuncAttributeMaxDynamicSharedMemorySize, GEMM_SMEM);
    cudaFuncSetAttribute(av_proj,    cudaFuncAttributeMaxDynamicSharedMemorySize, GEMM_SMEM);
    cudaFuncSetAttribute(av_pair,    cudaFuncAttributeMaxDynamicSharedMemorySize, GEMM_SMEM);

    // One-time fp16 conversion + output zeroing
    f2h_kernel<<<(ND * DIM) / 1024, 256>>>(emb_dest, Eh);
    f2h_kernel<<<(NS * DIM) / 1024, 256>>>(emb_src, Esh);
    f2h_kernel<<<(NS * DIM) / 1024, 256>>>(feat_src, Fh);
    zero_kernel<<<(ND * DIM) / 1024, 256>>>(out);
    const dim3 gT(DIM / 32, DIM / 32, NH), bT(32, 8);
    transpose_f2h<<<gT, bT>>>(Wq, Wqt);
    transpose_f2h<<<gT, bT>>>(Wk, Wkt);
    transpose_f2h<<<gT, bT>>>(Wv, Wvt);

    const dim3 blk(GEMM_THREADS);
    const dim3 gProj(DIM / BN, ND / BM, 6);     // (4, 32, 6)
    const dim3 gScore(NS / BN, ND / BM, 2);     // (32, 32, 2)
    const dim3 gAVProj(DIM / BN, ND / BM, 8);   // (4, 32, 8) = 1024 blocks
    const dim3 gAV(DIM / BN, ND / BM, 2);       // (4, 32, 2)
    const float scale = 0.04419417382415922f;   // 1/sqrt(512)

    // Prologue: projections for pair 0 (Vt into parity buffer 0)
    proj_all<<<gProj, blk, GEMM_SMEM>>>(
        Eh, Esh, Fh, Wqt, Wkt, Wvt, bq, bk, bv, Q, K, Vtp[0], 0);

    for (int i = 0; i < 4; ++i) {
        const int p = i & 1, pn = p ^ 1;

        score_pair<<<gScore, blk, GEMM_SMEM>>>(Q, K, S, scale);
        softmax_h<<<2 * ND, 256>>>(S);

        if (i < 3) {
            // AV of pair i fused with projections of pair i+1.
            // Q/K overwritten in place (score done); Vt goes to other buffer.
            av_proj<<<gAVProj, blk, GEMM_SMEM>>>(
                S, Vtp[p], out,
                Eh, Esh, Fh, Wqt, Wkt, Wvt, bq, bk, bv,
                Q, K, Vtp[pn], 2 * (i + 1));
        } else {
            av_pair<<<gAV, blk, GEMM_SMEM>>>(S, Vtp[p], out);
        }
    }
}